// round 7
// baseline (speedup 1.0000x reference)
#include <cuda_runtime.h>
#include <stdint.h>

// MaskPyramids single-pass, single-launch, level-specialized per block,
// all bulk stores 16B-aligned STG.128 (odd-parity rows handled by a +2
// element shift with float2 head/tail).
//
// grid = (14, 512): bx 0-9 -> level 200x200, bx 10-12 -> level 100x100,
// bx 13 -> levels 50/25/13 (tail, scalar).
//
// Rounding replicates XLA's div->reciprocal-mul rewrite (verified exact R3):
//   rint( fl( fl(p * fl(1/200)) * H ) ), all f32 RN-even.

#define N_INST   512
#define G        28
#define CTRK     13
#define PER_INST 53294   // 40000 + 10000 + 2500 + 625 + 169

__device__ __forceinline__ float mval(const float* __restrict__ mask,
                                      int si, int sj) {
    return ((unsigned)si < (unsigned)G && (unsigned)sj < (unsigned)G)
               ? __ldg(&mask[si * G + sj]) : 0.0f;
}

// Even-parity instances: off = 4*f4 is 16B-aligned, chunks never straddle rows.
template<int H, int BASE>
__device__ __forceinline__ void do_level_even(int chunk, int c0, int b0,
                                              const float* __restrict__ mask,
                                              float* __restrict__ outrow) {
    #pragma unroll
    for (int k = 0; k < 4; k++) {
        const int off = (chunk * 1024 + k * 256 + threadIdx.x) * 4;
        if (off < H * H) {
            const int row = off / H;            // compile-time magic div
            const int col = off - row * H;
            const int si  = row + c0;
            const int sj  = col - b0;
            float4 v = make_float4(0.f, 0.f, 0.f, 0.f);
            if ((unsigned)si < (unsigned)G && sj > -4 && sj < G) {
                const float* mrow = mask + si * G;
                if ((unsigned)(sj + 0) < (unsigned)G) v.x = __ldg(&mrow[sj + 0]);
                if ((unsigned)(sj + 1) < (unsigned)G) v.y = __ldg(&mrow[sj + 1]);
                if ((unsigned)(sj + 2) < (unsigned)G) v.z = __ldg(&mrow[sj + 2]);
                if ((unsigned)(sj + 3) < (unsigned)G) v.w = __ldg(&mrow[sj + 3]);
            }
            *reinterpret_cast<float4*>(outrow + BASE + off) = v;
        }
    }
}

// Odd-parity instances: off = 2 + 4*f4 is 16B-aligned. Chunk straddles a row
// exactly when col == H-2. Head (elems 0,1) and tail (elems H*H-2, H*H-1)
// are float2 stores by spare threads.
template<int H, int BASE>
__device__ __forceinline__ void do_level_odd(int chunk, int c0, int b0,
                                             const float* __restrict__ mask,
                                             float* __restrict__ outrow) {
    constexpr int NF4 = (H * H - 2) / 4;   // full shifted chunks
    #pragma unroll
    for (int k = 0; k < 4; k++) {
        const int f4 = chunk * 1024 + k * 256 + threadIdx.x;
        if (f4 < NF4) {
            const int off = 2 + f4 * 4;
            const int row = off / H;
            const int col = off - row * H;
            const int si  = row + c0;
            float4 v = make_float4(0.f, 0.f, 0.f, 0.f);
            if (col <= H - 4) {
                const int sj = col - b0;
                if ((unsigned)si < (unsigned)G && sj > -4 && sj < G) {
                    const float* mrow = mask + si * G;
                    if ((unsigned)(sj + 0) < (unsigned)G) v.x = __ldg(&mrow[sj + 0]);
                    if ((unsigned)(sj + 1) < (unsigned)G) v.y = __ldg(&mrow[sj + 1]);
                    if ((unsigned)(sj + 2) < (unsigned)G) v.z = __ldg(&mrow[sj + 2]);
                    if ((unsigned)(sj + 3) < (unsigned)G) v.w = __ldg(&mrow[sj + 3]);
                }
            } else {
                // col == H-2: elements (row,H-2),(row,H-1),(row+1,0),(row+1,1)
                v.x = mval(mask, si,     H - 2 - b0);
                v.y = mval(mask, si,     H - 1 - b0);
                v.z = mval(mask, si + 1, 0 - b0);
                v.w = mval(mask, si + 1, 1 - b0);
            }
            *reinterpret_cast<float4*>(outrow + BASE + off) = v;
        } else if (f4 == NF4) {
            // tail: elements H*H-2, H*H-1 (row H-1), 8B-aligned float2
            float2 t;
            t.x = mval(mask, H - 1 + c0, H - 2 - b0);
            t.y = mval(mask, H - 1 + c0, H - 1 - b0);
            *reinterpret_cast<float2*>(outrow + BASE + H * H - 2) = t;
        } else if (f4 == NF4 + 1) {
            // head: elements 0,1 (row 0), 8B-aligned float2
            float2 h;
            h.x = mval(mask, c0, 0 - b0);
            h.y = mval(mask, c0, 1 - b0);
            *reinterpret_cast<float2*>(outrow + BASE + 0) = h;
        }
    }
}

template<int H, int BASE, int N>
__device__ __forceinline__ void do_tail_level(float pp0, float pp1,
                                              const float* __restrict__ mask,
                                              float* __restrict__ outrow) {
    const int lh = (int)rintf(__fmul_rn(pp0, (float)H));
    const int lw = (int)rintf(__fmul_rn(pp1, (float)H));
    const int c0 = CTRK - lh;
    const int b0 = lw - CTRK;
    for (int idx = threadIdx.x; idx < N; idx += 256) {
        const int row = idx / H;                // compile-time magic div
        const int col = idx - row * H;
        outrow[BASE + idx] = mval(mask, row + c0, col - b0);
    }
}

__global__ void __launch_bounds__(256)
fused_kernel(const int* __restrict__ pos,
             const float* __restrict__ mask,
             float* __restrict__ out) {
    const int inst = blockIdx.y;
    const int bx   = blockIdx.x;

    const float recip = 0.005f;  // fl(1/200) bit-exactly
    const float pp0 = __fmul_rn((float)__ldg(&pos[2 * inst + 0]), recip);
    const float pp1 = __fmul_rn((float)__ldg(&pos[2 * inst + 1]), recip);

    float* outrow = out + inst * PER_INST;

    if (bx < 13) {
        int H200 = (bx < 10);
        // window center for the level this block serves
        const float Hf = H200 ? 200.f : 100.f;
        const int lh = (int)rintf(__fmul_rn(pp0, Hf));
        const int lw = (int)rintf(__fmul_rn(pp1, Hf));
        const int c0 = CTRK - lh;
        const int b0 = lw - CTRK;
        if ((inst & 1) == 0) {
            if (H200) do_level_even<200, 0>(bx, c0, b0, mask, outrow);
            else      do_level_even<100, 40000>(bx - 10, c0, b0, mask, outrow);
        } else {
            if (H200) do_level_odd<200, 0>(bx, c0, b0, mask, outrow);
            else      do_level_odd<100, 40000>(bx - 10, c0, b0, mask, outrow);
        }
    } else {
        do_tail_level<50, 50000, 2500>(pp0, pp1, mask, outrow);
        do_tail_level<25, 52500, 625>(pp0, pp1, mask, outrow);
        do_tail_level<13, 53125, 169>(pp0, pp1, mask, outrow);
    }
}

extern "C" void kernel_launch(void* const* d_in, const int* in_sizes, int n_in,
                              void* d_out, int out_size) {
    const int*   pos  = (const int*)d_in[0];      // int32 [512, 2]
    const float* mask = (const float*)d_in[1];    // float32 [28, 28]
    float*       out  = (float*)d_out;            // float32 [512, 53294]

    fused_kernel<<<dim3(14, N_INST), 256>>>(pos, mask, out);
}